// round 9
// baseline (speedup 1.0000x reference)
#include <cuda_runtime.h>
#include <cuda_bf16.h>

#define HH 28
#define WW 28
#define PAD 3
#define PW 35           // padded width (odd -> spread smem banks)
#define KK 7
#define NTAP 49
#define BATCH 512
#define NBR 8
#define FEAT 392        // 8 branches * 49

#define IMG_PER_BLK 4
#define STRIPS 56       // (28/7 cols) x (28/2 rows) strips per image
#define THREADS_A (IMG_PER_BLK * STRIPS)   // 224 = 7 full warps

typedef unsigned long long u64;
union F2U { float2 f; u64 u; };

__device__ float g_feat[BATCH * FEAT];
// float4-packed transposed weights: 4 consecutive K-steps per element.
__device__ float4 g_w1p[98 * 120];   // [i4][j]  w = W1[j][4*i4 .. 4*i4+3]
__device__ float4 g_w2p[30 * 84];    // [i4][j]
__device__ float4 g_w3p[21 * 10];    // [i4][j]
#define N_W1P (98 * 120)
#define N_W2P (30 * 84)
#define N_W3P (21 * 10)

#define FMA2(acc, a, b) asm("fma.rn.f32x2 %0, %1, %2, %0;" : "+l"(acc) : "l"(a), "l"(b))

// SMorph factorization:  out = (sum c1*u + sum c2*v) / (sum c1*v)
// v = exp(a*x), u = x*v, c1 = exp(a*w), c2 = w*c1.  Zero SAME-pad <=> (v,u)=(1,0).
// One block = 4 images x 1 branch; each thread owns a 7x2 output strip.
// (Round-4 version, verbatim: rel_err 7.4e-8.)
__global__ void __launch_bounds__(THREADS_A)
smorph_branch_kernel(const float* __restrict__ x,
                     const float* __restrict__ sm_w,      // [8,2,7,7]
                     const float* __restrict__ sm_alpha,  // [8,2]
                     const float* __restrict__ W1,        // for folded repack
                     const float* __restrict__ W2,
                     const float* __restrict__ W3)
{
    extern __shared__ float smem[];
    float* svu = smem;                              // [4][PW*PW][2]
    float* scp = svu + IMG_PER_BLK * PW * PW * 2;   // [49] float2 (c1,c1)
    float* sc2 = scp + 2 * NTAP;                    // [49]

    const int tid = threadIdx.x;
    const int b0  = blockIdx.x * IMG_PER_BLK;
    const int r   = blockIdx.y;

    // ---- folded one-shot weight repack (float4 of 4 consecutive K-steps) ----
    {
        int gid = blockIdx.y * gridDim.x + blockIdx.x;
        int t = gid * THREADS_A + tid;
        if (t < N_W1P) {
            int i4 = t / 120, j = t % 120;
            g_w1p[t] = *(const float4*)(W1 + j * FEAT + 4 * i4);
        } else if (t < N_W1P + N_W2P) {
            int q = t - N_W1P; int i4 = q / 84, j = q % 84;
            g_w2p[q] = *(const float4*)(W2 + j * 120 + 4 * i4);
        } else if (t < N_W1P + N_W2P + N_W3P) {
            int q = t - N_W1P - N_W2P; int i4 = q / 10, j = q % 10;
            g_w3p[q] = *(const float4*)(W3 + j * 84 + 4 * i4);
        }
    }

    const int img = tid / STRIPS;
    const int s   = tid % STRIPS;
    const int pr0 = (s / 4) * 2;   // strip top row   (0..26)
    const int pc0 = (s % 4) * 7;   // strip left col  (0,7,14,21)

    float2* myvu = (float2*)svu + img * (PW * PW);
    const float* xim = x + (b0 + img) * (HH * WW);

    const float a0 = sm_alpha[r * 2 + 0];
    const float a1 = sm_alpha[r * 2 + 1];

    // init to halo (v,u)=(1,0); interior overwritten below
    {
        float2* p = (float2*)svu;
        for (int i = tid; i < IMG_PER_BLK * PW * PW; i += THREADS_A)
            p[i] = make_float2(1.0f, 0.0f);
    }
    // layer-0 coefficients
    if (tid < NTAP) {
        float wv = sm_w[(r * 2 + 0) * NTAP + tid];
        float c1 = __expf(a0 * wv);
        scp[2 * tid] = c1; scp[2 * tid + 1] = c1;
        sc2[tid] = c1 * wv;
    }
    __syncthreads();

    // layer-0 interior fill
    for (int i = s; i < HH * WW; i += STRIPS) {
        float xi = xim[i];
        float vv = __expf(a0 * xi);
        int pr = i / WW, pc = i % WW;
        myvu[(pr + PAD) * PW + pc + PAD] = make_float2(vv, xi * vv);
    }
    __syncthreads();

    float y[2][7];

    #pragma unroll 1
    for (int L = 0; L < 2; L++) {
        // ---- conv: 7x2 strip, 8 input rows, coefficient rows cached in regs ----
        u64   acc2[2][7];    // packed (den = sum c1*v, num_u = sum c1*u)
        float accw[2][7];    // sum c2*v
        #pragma unroll
        for (int i = 0; i < 2; i++)
            #pragma unroll
            for (int j = 0; j < 7; j++) { acc2[i][j] = 0ull; accw[i][j] = 0.0f; }

        F2U cc_cur[7], cc_prev[7];
        float c2_cur[7], c2_prev[7];

        #pragma unroll
        for (int dy = 0; dy < 8; dy++) {
            F2U t[13];
            const float2* rowp = myvu + (pr0 + dy) * PW + pc0;
            #pragma unroll
            for (int k = 0; k < 13; k++) t[k].f = rowp[k];

            if (dy < 7) {
                #pragma unroll
                for (int dx = 0; dx < 7; dx++) {
                    cc_cur[dx].f = ((const float2*)scp)[dy * 7 + dx];
                    c2_cur[dx]   = sc2[dy * 7 + dx];
                }
                // sr = 0 uses tap row ky = dy
                #pragma unroll
                for (int dx = 0; dx < 7; dx++) {
                    u64 c = cc_cur[dx].u; float c2 = c2_cur[dx];
                    #pragma unroll
                    for (int scx = 0; scx < 7; scx++) {
                        FMA2(acc2[0][scx], c, t[dx + scx].u);
                        accw[0][scx] = fmaf(c2, t[dx + scx].f.x, accw[0][scx]);
                    }
                }
            }
            if (dy >= 1) {
                // sr = 1 uses tap row ky = dy-1 (cached from previous iteration)
                #pragma unroll
                for (int dx = 0; dx < 7; dx++) {
                    u64 c = cc_prev[dx].u; float c2 = c2_prev[dx];
                    #pragma unroll
                    for (int scx = 0; scx < 7; scx++) {
                        FMA2(acc2[1][scx], c, t[dx + scx].u);
                        accw[1][scx] = fmaf(c2, t[dx + scx].f.x, accw[1][scx]);
                    }
                }
            }
            if (dy < 7) {
                #pragma unroll
                for (int dx = 0; dx < 7; dx++) {
                    cc_prev[dx] = cc_cur[dx]; c2_prev[dx] = c2_cur[dx];
                }
            }
        }

        #pragma unroll
        for (int sr = 0; sr < 2; sr++)
            #pragma unroll
            for (int scx = 0; scx < 7; scx++) {
                F2U a; a.u = acc2[sr][scx];
                float den = a.f.x;
                float num = a.f.y + accw[sr][scx];
                y[sr][scx] = __fdividef(num, den);
            }
        __syncthreads();   // all conv reads of svu / coeff smem done

        if (L == 0) {
            // write layer-1 (v,u) directly; refresh coefficients for layer 1
            if (tid < NTAP) {
                float wv = sm_w[(r * 2 + 1) * NTAP + tid];
                float c1 = __expf(a1 * wv);
                scp[2 * tid] = c1; scp[2 * tid + 1] = c1;
                sc2[tid] = c1 * wv;
            }
            #pragma unroll
            for (int sr = 0; sr < 2; sr++)
                #pragma unroll
                for (int scx = 0; scx < 7; scx++) {
                    float yi = y[sr][scx];
                    float vv = __expf(a1 * yi);
                    myvu[(pr0 + sr + PAD) * PW + pc0 + scx + PAD] =
                        make_float2(vv, yi * vv);
                }
        } else {
            // final layer: store y as plain floats overlaid on this image's svu
            float* syf = (float*)myvu;
            #pragma unroll
            for (int sr = 0; sr < 2; sr++)
                #pragma unroll
                for (int scx = 0; scx < 7; scx++)
                    syf[(pr0 + sr) * WW + pc0 + scx] = y[sr][scx];
        }
        __syncthreads();
    }

    // ---- 4x4 avg pool (== two 2x2 pools) -> [7,7] features ----
    if (s < NTAP) {
        const float* syf = (const float*)myvu;
        int qr = s / 7, qc = s % 7;
        float acc = 0.0f;
        #pragma unroll
        for (int dy = 0; dy < 4; dy++)
            #pragma unroll
            for (int dx = 0; dx < 4; dx++)
                acc += syf[(qr * 4 + dy) * WW + qc * 4 + dx];
        g_feat[(b0 + img) * FEAT + r * NTAP + s] = acc * (1.0f / 16.0f);
    }
}

__device__ __forceinline__ float sigf(float z) {
    return 1.0f / (1.0f + __expf(-z));
}

// Fused 3-layer sigmoid MLP with ALL weights smem-resident.
// 64 blocks x 512 threads, 8 batch rows per block.
// Stage W1 (188KB) cooperatively -> compute layer 1 from smem only;
// restage W2 into the same buffer -> layer 2; W3 staged upfront.
// Per-row fmaf nesting/order identical to Round 4 (rel_err 7.4e-8).
#define MROWS 8
#define MLP_SMEM_BYTES ((N_W1P + N_W3P) * 16 + (MROWS * (FEAT + 120 + 84)) * 4)

#define MLP_GROUP4(GW, SA, SB, I4, STRIDE)                                         \
    {                                                                              \
        float4 w0 = GW[(I4 + 0) * STRIDE + j];                                     \
        float4 w1 = GW[(I4 + 1) * STRIDE + j];                                     \
        float4 w2 = GW[(I4 + 2) * STRIDE + j];                                     \
        float4 w3 = GW[(I4 + 3) * STRIDE + j];                                     \
        float4 sa0 = *(const float4*)&SA[(I4 + 0) * 4];                            \
        float4 sb0 = *(const float4*)&SB[(I4 + 0) * 4];                            \
        float4 sa1 = *(const float4*)&SA[(I4 + 1) * 4];                            \
        float4 sb1 = *(const float4*)&SB[(I4 + 1) * 4];                            \
        float4 sa2 = *(const float4*)&SA[(I4 + 2) * 4];                            \
        float4 sb2 = *(const float4*)&SB[(I4 + 2) * 4];                            \
        float4 sa3 = *(const float4*)&SA[(I4 + 3) * 4];                            \
        float4 sb3 = *(const float4*)&SB[(I4 + 3) * 4];                            \
        accA = fmaf(w0.x, sa0.x, fmaf(w0.y, sa0.y, fmaf(w0.z, sa0.z, fmaf(w0.w, sa0.w, accA)))); \
        accB = fmaf(w0.x, sb0.x, fmaf(w0.y, sb0.y, fmaf(w0.z, sb0.z, fmaf(w0.w, sb0.w, accB)))); \
        accA = fmaf(w1.x, sa1.x, fmaf(w1.y, sa1.y, fmaf(w1.z, sa1.z, fmaf(w1.w, sa1.w, accA)))); \
        accB = fmaf(w1.x, sb1.x, fmaf(w1.y, sb1.y, fmaf(w1.z, sb1.z, fmaf(w1.w, sb1.w, accB)))); \
        accA = fmaf(w2.x, sa2.x, fmaf(w2.y, sa2.y, fmaf(w2.z, sa2.z, fmaf(w2.w, sa2.w, accA)))); \
        accB = fmaf(w2.x, sb2.x, fmaf(w2.y, sb2.y, fmaf(w2.z, sb2.z, fmaf(w2.w, sb2.w, accB)))); \
        accA = fmaf(w3.x, sa3.x, fmaf(w3.y, sa3.y, fmaf(w3.z, sa3.z, fmaf(w3.w, sa3.w, accA)))); \
        accB = fmaf(w3.x, sb3.x, fmaf(w3.y, sb3.y, fmaf(w3.z, sb3.z, fmaf(w3.w, sb3.w, accB)))); \
    }

__global__ void __launch_bounds__(512) mlp_kernel(
    const float* __restrict__ b1,
    const float* __restrict__ b2,
    const float* __restrict__ b3,
    float* __restrict__ out)
{
    extern __shared__ float4 mlp_smem[];
    float4* swb = mlp_smem;                    // N_W1P (reused for W2)
    float4* sw3 = swb + N_W1P;                 // N_W3P
    float*  sf  = (float*)(sw3 + N_W3P);       // [MROWS][FEAT]
    float*  sh1 = sf + MROWS * FEAT;           // [MROWS][120]
    float*  sh2 = sh1 + MROWS * 120;           // [MROWS][84]

    const int tid = threadIdx.x;
    const int b0  = blockIdx.x * MROWS;
    const int j   = tid & 127;           // output-neuron lane
    const int rg  = tid >> 7;            // 0..3
    const int rA  = rg * 2, rB = rA + 1;

    // ---- stage W1, W3, features (all loads independent) ----
    for (int i = tid; i < N_W1P; i += 512) swb[i] = g_w1p[i];
    if (tid < N_W3P) sw3[tid] = g_w3p[tid];
    {
        const float4* src = (const float4*)(g_feat + b0 * FEAT);
        #pragma unroll
        for (int i = tid; i < MROWS * FEAT / 4; i += 512)
            ((float4*)sf)[i] = src[i];
    }
    __syncthreads();

    // ---- 392 -> 120 : 98 i4-groups = 24x4 + 2 ----
    if (j < 120) {
        float bb = b1[j];
        float accA = bb, accB = bb;
        const float* SA = sf + rA * FEAT;
        const float* SB = sf + rB * FEAT;
        #pragma unroll 6
        for (int g = 0; g < 24; g++)
            MLP_GROUP4(swb, SA, SB, g * 4, 120)
        #pragma unroll
        for (int i4 = 96; i4 < 98; i4++) {
            float4 w  = swb[i4 * 120 + j];
            float4 sa = *(const float4*)&SA[i4 * 4];
            float4 sb = *(const float4*)&SB[i4 * 4];
            accA = fmaf(w.x, sa.x, fmaf(w.y, sa.y, fmaf(w.z, sa.z, fmaf(w.w, sa.w, accA))));
            accB = fmaf(w.x, sb.x, fmaf(w.y, sb.y, fmaf(w.z, sb.z, fmaf(w.w, sb.w, accB))));
        }
        sh1[rA * 120 + j] = sigf(accA);
        sh1[rB * 120 + j] = sigf(accB);
    }
    __syncthreads();

    // ---- restage W2 over W1's buffer ----
    for (int i = tid; i < N_W2P; i += 512) swb[i] = g_w2p[i];
    __syncthreads();

    // ---- 120 -> 84 : 30 i4-groups = 7x4 + 2 ----
    if (j < 84) {
        float bb = b2[j];
        float accA = bb, accB = bb;
        const float* SA = sh1 + rA * 120;
        const float* SB = sh1 + rB * 120;
        #pragma unroll 7
        for (int g = 0; g < 7; g++)
            MLP_GROUP4(swb, SA, SB, g * 4, 84)
        #pragma unroll
        for (int i4 = 28; i4 < 30; i4++) {
            float4 w  = swb[i4 * 84 + j];
            float4 sa = *(const float4*)&SA[i4 * 4];
            float4 sb = *(const float4*)&SB[i4 * 4];
            accA = fmaf(w.x, sa.x, fmaf(w.y, sa.y, fmaf(w.z, sa.z, fmaf(w.w, sa.w, accA))));
            accB = fmaf(w.x, sb.x, fmaf(w.y, sb.y, fmaf(w.z, sb.z, fmaf(w.w, sb.w, accB))));
        }
        sh2[rA * 84 + j] = sigf(accA);
        sh2[rB * 84 + j] = sigf(accB);
    }
    __syncthreads();

    // ---- 84 -> 10 ----  (80 threads: one (row, j) scalar dot each)
    if (tid < 80) {
        const int jj = tid % 10;
        const int rr = tid / 10;
        float acc = b3[jj];
        const float* S = sh2 + rr * 84;
        #pragma unroll 7
        for (int i4 = 0; i4 < 21; i4++) {
            float4 w = sw3[i4 * 10 + jj];
            float4 s = *(const float4*)&S[i4 * 4];
            acc = fmaf(w.x, s.x, fmaf(w.y, s.y, fmaf(w.z, s.z, fmaf(w.w, s.w, acc))));
        }
        out[(b0 + rr) * 10 + jj] = sigf(acc);
    }
}

extern "C" void kernel_launch(void* const* d_in, const int* in_sizes, int n_in,
                              void* d_out, int out_size)
{
    const float* x        = (const float*)d_in[0];
    const float* sm_w     = (const float*)d_in[1];
    const float* sm_alpha = (const float*)d_in[2];
    const float* W1       = (const float*)d_in[3];
    const float* b1       = (const float*)d_in[4];
    const float* W2       = (const float*)d_in[5];
    const float* b2       = (const float*)d_in[6];
    const float* W3       = (const float*)d_in[7];
    const float* b3       = (const float*)d_in[8];
    float* out = (float*)d_out;

    static int attr_done = 0;
    if (!attr_done) {
        cudaFuncSetAttribute(mlp_kernel,
                             cudaFuncAttributeMaxDynamicSharedMemorySize,
                             MLP_SMEM_BYTES);
        attr_done = 1;
    }

    const int smem_bytes =
        (IMG_PER_BLK * PW * PW * 2 + 3 * NTAP) * (int)sizeof(float);  // ~39.8KB

    dim3 gridA(BATCH / IMG_PER_BLK, NBR);   // (128, 8)
    smorph_branch_kernel<<<gridA, THREADS_A, smem_bytes>>>(
        x, sm_w, sm_alpha, W1, W2, W3);

    mlp_kernel<<<BATCH / MROWS, 512, MLP_SMEM_BYTES>>>(b1, b2, b3, out);
}